// round 3
// baseline (speedup 1.0000x reference)
#include <cuda_runtime.h>
#include <cstdint>

#define NB 8
#define NC 256
#define NQ 4096
#define NK 4096
#define KNN 8
#define NSPLIT 8                  // threads per query in knn
#define KCHUNK 2048

// Scratch (static __device__ globals — allocation-free per harness rules)
__device__ float g_KT[(size_t)NB * NK * NC];   // key_features transposed (B,NK,C)
__device__ int   g_idx[(size_t)NB * NQ * KNN]; // knn indices

#define TR_BLOCKS (NB * (NK / 32) * (NC / 32))        // 8192
#define KNN_QPB   32                                   // queries per knn block
#define KNN_BLOCKS (NB * (NQ / KNN_QPB))               // 1024

// ---------------------------------------------------------------------------
// Fused prep kernel: blocks [0, TR_BLOCKS) transpose key_features,
// blocks [TR_BLOCKS, TR_BLOCKS+KNN_BLOCKS) compute kNN indices.
// Both independent -> overlap memory-bound transpose with compute-bound knn.
// ---------------------------------------------------------------------------
__global__ void prep_kernel(const float* __restrict__ qc,
                            const float* __restrict__ kc,
                            const float* __restrict__ kf) {
    __shared__ __align__(16) unsigned char smem_raw[KCHUNK * 16]; // 32KB union
    int tid = threadIdx.x;  // 256

    if (blockIdx.x < TR_BLOCKS) {
        // ---------------- transpose (B,C,NK) -> (B,NK,C) ----------------
        float (*t)[33] = reinterpret_cast<float (*)[33]>(smem_raw);
        int idx = blockIdx.x;
        int b   = idx >> 10;            // / 1024
        int rem = idx & 1023;
        int n0  = (rem & 127) * 32;     // NK tile
        int c0  = (rem >> 7) * 32;      // NC tile
        int tx = tid & 31, ty0 = tid >> 5;  // (32, 8)
#pragma unroll
        for (int dy = 0; dy < 32; dy += 8) {
            int ty = ty0 + dy;
            t[ty][tx] = kf[((size_t)b * NC + c0 + ty) * NK + n0 + tx];
        }
        __syncthreads();
#pragma unroll
        for (int dy = 0; dy < 32; dy += 8) {
            int ty = ty0 + dy;
            g_KT[((size_t)b * NK + n0 + ty) * NC + c0 + tx] = t[tx][ty];
        }
        return;
    }

    // ---------------- kNN: 8 threads per query, split over keys ----------
    float4* sk = reinterpret_cast<float4*>(smem_raw);   // KCHUNK float4
    int bid = blockIdx.x - TR_BLOCKS;
    int b    = bid >> 7;                 // / (NQ/32)
    int qblk = bid & 127;
    int ql   = tid >> 3;                 // query within block [0,32)
    int s    = tid & (NSPLIT - 1);       // split id [0,8)
    int n    = qblk * KNN_QPB + ql;

    const float* kb = kc + (size_t)b * 3 * NK;
    const float* qb = qc + (size_t)b * 3 * NQ;
    float qx = qb[n], qy = qb[NQ + n], qz = qb[2 * NQ + n];
    // qq: XLA square+reduce, separately rounded, no fma
    float qq = __fadd_rn(__fadd_rn(__fmul_rn(qx, qx), __fmul_rn(qy, qy)),
                         __fmul_rn(qz, qz));

    float bd[KNN];
    int   bi[KNN];
#pragma unroll
    for (int i = 0; i < KNN; i++) { bd[i] = 3.4e38f; bi[i] = 0; }

    for (int m0 = 0; m0 < NK; m0 += KCHUNK) {
        __syncthreads();
        for (int m = tid; m < KCHUNK; m += 256) {
            float x = kb[m0 + m];
            float y = kb[NK + m0 + m];
            float z = kb[2 * NK + m0 + m];
            float kk = __fadd_rn(__fadd_rn(__fmul_rn(x, x), __fmul_rn(y, y)),
                                 __fmul_rn(z, z));
            sk[m] = make_float4(x, y, z, kk);
        }
        __syncthreads();
        // interleaved split: thread s scans indices s, s+8, s+16, ...
        // (ascending within thread -> stable; consecutive s lanes hit
        //  contiguous 16B lines -> conflict-free broadcast LDS)
#pragma unroll 4
        for (int i = 0; i < KCHUNK / NSPLIT; i++) {
            int m = i * NSPLIT + s;
            float4 k4 = sk[m];
            // XLA sequence: dot = fma(qz,kz, fma(qy,ky, rn(qx*kx)))
            float dot = __fmaf_rn(qz, k4.z,
                         __fmaf_rn(qy, k4.y, __fmul_rn(qx, k4.x)));
            float t2 = __fsub_rn(qq, 2.0f * dot);   // 2*dot exact
            float d  = __fadd_rn(t2, k4.w);
            if (d < bd[KNN - 1]) {
                bd[KNN - 1] = d;
                bi[KNN - 1] = m0 + m;
#pragma unroll
                for (int j = KNN - 1; j > 0; j--) {
                    if (bd[j] < bd[j - 1]) {
                        float td = bd[j]; bd[j] = bd[j - 1]; bd[j - 1] = td;
                        int   ti = bi[j]; bi[j] = bi[j - 1]; bi[j - 1] = ti;
                    }
                }
            }
        }
    }

    // ---- merge 8 partial top-8 lists per query (lexicographic (d, idx)) ----
    __syncthreads();
    float* md = reinterpret_cast<float*>(smem_raw);            // 2048 floats
    int*   mi = reinterpret_cast<int*>(smem_raw + 8192);       // 2048 ints
#pragma unroll
    for (int j = 0; j < KNN; j++) {
        md[tid * KNN + j] = bd[j];
        mi[tid * KNN + j] = bi[j];
    }
    __syncthreads();
    if (s == 0) {
        float fd[KNN]; int fi[KNN];
#pragma unroll
        for (int i = 0; i < KNN; i++) { fd[i] = 3.4e38f; fi[i] = 0x7fffffff; }
        int base = ql * NSPLIT * KNN;
        for (int c = 0; c < NSPLIT * KNN; c++) {
            float d = md[base + c];
            int   i = mi[base + c];
            if (d < fd[KNN - 1] || (d == fd[KNN - 1] && i < fi[KNN - 1])) {
                fd[KNN - 1] = d; fi[KNN - 1] = i;
#pragma unroll
                for (int j = KNN - 1; j > 0; j--) {
                    bool lt = fd[j] < fd[j - 1] ||
                              (fd[j] == fd[j - 1] && fi[j] < fi[j - 1]);
                    if (lt) {
                        float td = fd[j]; fd[j] = fd[j - 1]; fd[j - 1] = td;
                        int   ti = fi[j]; fi[j] = fi[j - 1]; fi[j - 1] = ti;
                    }
                }
            }
        }
        int* o = g_idx + ((size_t)b * NQ + n) * KNN;
#pragma unroll
        for (int i = 0; i < KNN; i++) o[i] = fi[i];
    }
}

// ---------------------------------------------------------------------------
// Gather + subtract + write (shared-staged for full write coalescing).
// out[b][c][n][k]     = KT[b][idx[n][k]][c] - qf[b][c][n]
// out[b][c+256][n][k] = qf[b][c][n]
// ---------------------------------------------------------------------------
#define NT 16                    // queries per CTA
#define NP (NT * KNN)            // 128 (n,k) pairs
#define CCH 64                   // channel chunk

__global__ void gather_kernel(const float* __restrict__ qf,
                              float* __restrict__ out) {
    __shared__ float S[CCH][NP + 1];
    __shared__ float Qs[NT][CCH + 1];
    __shared__ int   sidx[NP];

    int b   = blockIdx.y;
    int n0  = blockIdx.x * NT;
    int tid = threadIdx.x;  // 256

    if (tid < NP) sidx[tid] = g_idx[((size_t)b * NQ + n0) * KNN + tid];
    __syncthreads();

    const float* KTb = g_KT + (size_t)b * NK * NC;

    for (int c0 = 0; c0 < NC; c0 += CCH) {
        if (c0) __syncthreads();

        for (int i = tid; i < NP * (CCH / 4); i += 256) {
            int p  = i >> 4;
            int c4 = (i & 15) * 4;
            float4 v = *reinterpret_cast<const float4*>(
                &KTb[(size_t)sidx[p] * NC + c0 + c4]);
            S[c4 + 0][p] = v.x;
            S[c4 + 1][p] = v.y;
            S[c4 + 2][p] = v.z;
            S[c4 + 3][p] = v.w;
        }
        for (int i = tid; i < NT * CCH; i += 256) {
            int c = i >> 4, j = i & 15;
            Qs[j][c] = qf[((size_t)b * NC + c0 + c) * NQ + n0 + j];
        }
        __syncthreads();

        for (int i = tid; i < CCH * (NP / 4); i += 256) {
            int c = i >> 5;
            int p = (i & 31) * 4;
            float q = Qs[p >> 3][c];
            float4 d, qv;
            d.x = S[c][p + 0] - q;
            d.y = S[c][p + 1] - q;
            d.z = S[c][p + 2] - q;
            d.w = S[c][p + 3] - q;
            qv.x = q; qv.y = q; qv.z = q; qv.w = q;
            size_t ob = (((size_t)b * (2 * NC) + c0 + c) * NQ + n0) * KNN + p;
            // streaming stores: 512MB with zero reuse — keep L2 for KT
            __stcs(reinterpret_cast<float4*>(&out[ob]), d);
            __stcs(reinterpret_cast<float4*>(&out[ob + (size_t)NC * NQ * KNN]), qv);
        }
    }
}

// ---------------------------------------------------------------------------
extern "C" void kernel_launch(void* const* d_in, const int* in_sizes, int n_in,
                              void* d_out, int out_size) {
    const float* query_coords   = (const float*)d_in[0]; // (B,3,NQ)
    const float* query_features = (const float*)d_in[1]; // (B,C,NQ)
    const float* key_coords     = (const float*)d_in[2]; // (B,3,NK)
    const float* key_features   = (const float*)d_in[3]; // (B,C,NK)
    float* out = (float*)d_out;                          // (B,2C,NQ,K)

    prep_kernel<<<TR_BLOCKS + KNN_BLOCKS, 256>>>(query_coords, key_coords,
                                                 key_features);
    {
        dim3 grid(NQ / NT, NB);
        gather_kernel<<<grid, 256>>>(query_features, out);
    }
}

// round 4
// speedup vs baseline: 1.0682x; 1.0682x over previous
#include <cuda_runtime.h>
#include <cstdint>

#define NB 8
#define NC 256
#define NQ 4096
#define NK 4096
#define KNN 8
#define KCHUNK 2048
#define MARGIN 1e-3f

// Scratch (static __device__ globals — allocation-free per harness rules)
__device__ float g_KT[(size_t)NB * NK * NC];   // key_features transposed (B,NK,C)
__device__ int   g_idx[(size_t)NB * NQ * KNN]; // knn indices

// ---- packed f32x2 helpers (sm_103a) ----
#define MUL2(o, a, b)    asm("mul.rn.f32x2 %0, %1, %2;"     : "=l"(o) : "l"(a), "l"(b))
#define ADD2(o, a, b)    asm("add.rn.f32x2 %0, %1, %2;"     : "=l"(o) : "l"(a), "l"(b))
#define FMA2(o, a, b, c) asm("fma.rn.f32x2 %0, %1, %2, %3;" : "=l"(o) : "l"(a), "l"(b), "l"(c))
#define PACK2(o, lo, hi) asm("mov.b64 %0, {%1, %2};" : "=l"(o) : "f"(lo), "f"(hi))
#define UNPACK2(lo, hi, v) asm("mov.b64 {%0, %1}, %2;" : "=f"(lo), "=f"(hi) : "l"(v))

// ---------------------------------------------------------------------------
// Kernel 1: transpose key_features (B,C,NK) -> g_KT (B,NK,C)
// ---------------------------------------------------------------------------
__global__ void transpose_kf(const float* __restrict__ kf) {
    __shared__ float t[32][33];
    int b  = blockIdx.z;
    int n0 = blockIdx.x * 32;
    int c0 = blockIdx.y * 32;
    int tx = threadIdx.x, ty0 = threadIdx.y;
#pragma unroll
    for (int dy = 0; dy < 32; dy += 8) {
        int ty = ty0 + dy;
        t[ty][tx] = kf[((size_t)b * NC + c0 + ty) * NK + n0 + tx];
    }
    __syncthreads();
#pragma unroll
    for (int dy = 0; dy < 32; dy += 8) {
        int ty = ty0 + dy;
        g_KT[((size_t)b * NK + n0 + ty) * NC + c0 + tx] = t[tx][ty];
    }
}

// ---------------------------------------------------------------------------
// Kernel 2: kNN, 1 thread per query (long scans -> rare warp-divergent
// inserts). Hot loop: packed f32x2 filter over key PAIRS; exact XLA-rounded
// distance only for candidates within MARGIN of the current 8th best.
// dot from the packed fma chain is bit-identical to the scalar XLA chain:
//   dot = fma(qz,kz, fma(qy,ky, rn(qx*kx)))
//   d   = rn(rn(qq - 2*dot) + kk)           (exact path)
//   d'  = fma(dot, -2, rn(qq + kk))         (filter; |d'-d| <= ~4 ulp)
// Strict '<' insert over ascending key order => jax.lax.top_k tie behavior.
// ---------------------------------------------------------------------------
#define INSERT_EXACT(DOT, KK, IDX)                                            \
    do {                                                                      \
        float _d = __fadd_rn(__fsub_rn(qq, 2.0f * (DOT)), (KK));              \
        if (_d < bd[KNN - 1]) {                                               \
            bd[KNN - 1] = _d; bi[KNN - 1] = (IDX);                            \
            _Pragma("unroll")                                                 \
            for (int _j = KNN - 1; _j > 0; _j--) {                            \
                if (bd[_j] < bd[_j - 1]) {                                    \
                    float _td = bd[_j]; bd[_j] = bd[_j - 1]; bd[_j - 1] = _td;\
                    int _ti = bi[_j]; bi[_j] = bi[_j - 1]; bi[_j - 1] = _ti;  \
                }                                                             \
            }                                                                 \
            thrM = bd[KNN - 1] + MARGIN;                                      \
        }                                                                     \
    } while (0)

__global__ void knn_kernel(const float* __restrict__ qc,
                           const float* __restrict__ kc) {
    // pair-packed key tiles: sA[p] = (x0,x1,y0,y1), sB[p] = (z0,z1,kk0,kk1)
    __shared__ __align__(16) float sA[(KCHUNK / 2) * 4];  // 16KB
    __shared__ __align__(16) float sB[(KCHUNK / 2) * 4];  // 16KB

    int b = blockIdx.y;
    int n = blockIdx.x * blockDim.x + threadIdx.x;

    const float* kb = kc + (size_t)b * 3 * NK;
    const float* qb = qc + (size_t)b * 3 * NQ;
    float qx = qb[n], qy = qb[NQ + n], qz = qb[2 * NQ + n];
    float qq = __fadd_rn(__fadd_rn(__fmul_rn(qx, qx), __fmul_rn(qy, qy)),
                         __fmul_rn(qz, qz));

    unsigned long long qx2, qy2, qz2, qq2, m2;
    PACK2(qx2, qx, qx);
    PACK2(qy2, qy, qy);
    PACK2(qz2, qz, qz);
    PACK2(qq2, qq, qq);
    PACK2(m2, -2.0f, -2.0f);

    float bd[KNN];
    int   bi[KNN];
#pragma unroll
    for (int i = 0; i < KNN; i++) { bd[i] = 3.4e38f; bi[i] = 0; }
    float thrM = 3.4e38f;

    for (int m0 = 0; m0 < NK; m0 += KCHUNK) {
        __syncthreads();
        // stage pair-packed keys (float2 loads, coalesced)
        for (int p = threadIdx.x; p < KCHUNK / 2; p += blockDim.x) {
            int m = m0 + 2 * p;
            float2 xx = *reinterpret_cast<const float2*>(&kb[m]);
            float2 yy = *reinterpret_cast<const float2*>(&kb[NK + m]);
            float2 zz = *reinterpret_cast<const float2*>(&kb[2 * NK + m]);
            float k0 = __fadd_rn(__fadd_rn(__fmul_rn(xx.x, xx.x),
                                           __fmul_rn(yy.x, yy.x)),
                                 __fmul_rn(zz.x, zz.x));
            float k1 = __fadd_rn(__fadd_rn(__fmul_rn(xx.y, xx.y),
                                           __fmul_rn(yy.y, yy.y)),
                                 __fmul_rn(zz.y, zz.y));
            reinterpret_cast<float4*>(sA)[p] = make_float4(xx.x, xx.y, yy.x, yy.y);
            reinterpret_cast<float4*>(sB)[p] = make_float4(zz.x, zz.y, k0, k1);
        }
        __syncthreads();

#pragma unroll 4
        for (int p = 0; p < KCHUNK / 2; p++) {
            ulonglong2 a  = reinterpret_cast<const ulonglong2*>(sA)[p];
            ulonglong2 bz = reinterpret_cast<const ulonglong2*>(sB)[p];
            // a.x=(x0,x1) a.y=(y0,y1) bz.x=(z0,z1) bz.y=(kk0,kk1)
            unsigned long long dot2, s2, d2;
            MUL2(dot2, qx2, a.x);
            FMA2(dot2, qy2, a.y, dot2);
            FMA2(dot2, qz2, bz.x, dot2);   // halves == scalar XLA dot chain
            ADD2(s2, qq2, bz.y);
            FMA2(d2, dot2, m2, s2);        // filter distance d'
            float d0, d1;
            UNPACK2(d0, d1, d2);
            if (d0 < thrM) {
                float dot0, dot1, kk0, kk1;
                UNPACK2(dot0, dot1, dot2);
                UNPACK2(kk0, kk1, bz.y);
                INSERT_EXACT(dot0, kk0, m0 + 2 * p);
            }
            if (d1 < thrM) {
                float dot0, dot1, kk0, kk1;
                UNPACK2(dot0, dot1, dot2);
                UNPACK2(kk0, kk1, bz.y);
                INSERT_EXACT(dot1, kk1, m0 + 2 * p + 1);
            }
        }
    }

    int* o = g_idx + ((size_t)b * NQ + n) * KNN;
#pragma unroll
    for (int i = 0; i < KNN; i++) o[i] = bi[i];
}

// ---------------------------------------------------------------------------
// Kernel 3: gather + subtract + write (shared-staged, coalesced, streaming).
// out[b][c][n][k]     = KT[b][idx[n][k]][c] - qf[b][c][n]
// out[b][c+256][n][k] = qf[b][c][n]
// ---------------------------------------------------------------------------
#define NT 16
#define NP (NT * KNN)
#define CCH 64

__global__ void gather_kernel(const float* __restrict__ qf,
                              float* __restrict__ out) {
    __shared__ float S[CCH][NP + 1];
    __shared__ float Qs[NT][CCH + 1];
    __shared__ int   sidx[NP];

    int b   = blockIdx.y;
    int n0  = blockIdx.x * NT;
    int tid = threadIdx.x;  // 256

    if (tid < NP) sidx[tid] = g_idx[((size_t)b * NQ + n0) * KNN + tid];
    __syncthreads();

    const float* KTb = g_KT + (size_t)b * NK * NC;

    for (int c0 = 0; c0 < NC; c0 += CCH) {
        if (c0) __syncthreads();

#pragma unroll
        for (int i = tid; i < NP * (CCH / 4); i += 256) {
            int p  = i >> 4;
            int c4 = (i & 15) * 4;
            float4 v = *reinterpret_cast<const float4*>(
                &KTb[(size_t)sidx[p] * NC + c0 + c4]);
            S[c4 + 0][p] = v.x;
            S[c4 + 1][p] = v.y;
            S[c4 + 2][p] = v.z;
            S[c4 + 3][p] = v.w;
        }
#pragma unroll
        for (int i = tid; i < NT * CCH; i += 256) {
            int c = i >> 4, j = i & 15;
            Qs[j][c] = qf[((size_t)b * NC + c0 + c) * NQ + n0 + j];
        }
        __syncthreads();

#pragma unroll
        for (int i = tid; i < CCH * (NP / 4); i += 256) {
            int c = i >> 5;
            int p = (i & 31) * 4;
            float q = Qs[p >> 3][c];
            float4 d, qv;
            d.x = S[c][p + 0] - q;
            d.y = S[c][p + 1] - q;
            d.z = S[c][p + 2] - q;
            d.w = S[c][p + 3] - q;
            qv.x = q; qv.y = q; qv.z = q; qv.w = q;
            size_t ob = (((size_t)b * (2 * NC) + c0 + c) * NQ + n0) * KNN + p;
            __stcs(reinterpret_cast<float4*>(&out[ob]), d);
            __stcs(reinterpret_cast<float4*>(&out[ob + (size_t)NC * NQ * KNN]), qv);
        }
    }
}

// ---------------------------------------------------------------------------
extern "C" void kernel_launch(void* const* d_in, const int* in_sizes, int n_in,
                              void* d_out, int out_size) {
    const float* query_coords   = (const float*)d_in[0]; // (B,3,NQ)
    const float* query_features = (const float*)d_in[1]; // (B,C,NQ)
    const float* key_coords     = (const float*)d_in[2]; // (B,3,NK)
    const float* key_features   = (const float*)d_in[3]; // (B,C,NK)
    float* out = (float*)d_out;                          // (B,2C,NQ,K)

    {
        dim3 grid(NK / 32, NC / 32, NB);
        dim3 block(32, 8);
        transpose_kf<<<grid, block>>>(key_features);
    }
    {
        dim3 grid(NQ / 128, NB);
        knn_kernel<<<grid, 128>>>(query_coords, key_coords);
    }
    {
        dim3 grid(NQ / NT, NB);
        gather_kernel<<<grid, 256>>>(query_features, out);
    }
}

// round 5
// speedup vs baseline: 1.4481x; 1.3556x over previous
#include <cuda_runtime.h>
#include <cstdint>

#define NB 8
#define NC 256
#define NQ 4096
#define NK 4096
#define KNN 8
#define KCHUNK 2048
#define FULLM 0xffffffffu

// Scratch (static __device__ globals — allocation-free per harness rules)
__device__ float g_KT[(size_t)NB * NK * NC];   // key_features transposed (B,NK,C)
__device__ int   g_idx[(size_t)NB * NQ * KNN]; // knn indices

#define QPB 16                                  // queries per knn block (8 warps x 2)
#define KNN_BLOCKS (NB * (NQ / QPB))            // 2048
#define TR_BLOCKS  (NB * (NK / 32) * (NC / 32)) // 8192

// ---------------------------------------------------------------------------
// Fused prep kernel.
// Blocks [0, KNN_BLOCKS): warp-cooperative kNN (2 queries per warp).
// Blocks [KNN_BLOCKS, +TR_BLOCKS): transpose key_features (B,C,NK)->(B,NK,C).
// kNN blocks first: they are the long pole; transpose overlaps underneath.
//
// kNN semantics (bit-exact vs XLA reference):
//   qq  = rn(rn(rn(x*x)+rn(y*y))+rn(z*z))           (no fma)
//   dot = fma(qz,kz, fma(qy,ky, rn(qx*kx)))         (GEMM k-ascending chain)
//   d   = rn(rn(qq - 2*dot) + kk)                   (2*dot exact)
// Keys processed in ascending index order (chunks asc, iters asc, ffs asc)
// with strict '<' entry and strictly-greater shift in the sorted list
// => identical tie behavior to jax.lax.top_k.
// Top-8 list is shuffle-distributed: lane l (l<8) holds A's l-th best,
// lanes 8..15 hold B's. Inserts are warp-uniform (no divergence).
// ---------------------------------------------------------------------------
__global__ void prep_kernel(const float* __restrict__ qc,
                            const float* __restrict__ kc,
                            const float* __restrict__ kf) {
    __shared__ __align__(16) unsigned char smem_raw[KCHUNK * 16]; // 32KB
    int tid = threadIdx.x;  // 256

    if (blockIdx.x >= KNN_BLOCKS) {
        // ---------------- transpose (B,C,NK) -> (B,NK,C) ----------------
        float (*t)[33] = reinterpret_cast<float (*)[33]>(smem_raw);
        int idx = blockIdx.x - KNN_BLOCKS;
        int b   = idx >> 10;
        int rem = idx & 1023;
        int n0  = (rem & 127) * 32;
        int c0  = (rem >> 7) * 32;
        int tx = tid & 31, ty0 = tid >> 5;
#pragma unroll
        for (int dy = 0; dy < 32; dy += 8) {
            int ty = ty0 + dy;
            t[ty][tx] = kf[((size_t)b * NC + c0 + ty) * NK + n0 + tx];
        }
        __syncthreads();
#pragma unroll
        for (int dy = 0; dy < 32; dy += 8) {
            int ty = ty0 + dy;
            g_KT[((size_t)b * NK + n0 + ty) * NC + c0 + tx] = t[tx][ty];
        }
        return;
    }

    // ----------------------------- kNN ----------------------------------
    float4* sk = reinterpret_cast<float4*>(smem_raw);  // KCHUNK float4
    int bid  = blockIdx.x;
    int b    = bid >> 8;          // / (NQ/QPB = 256)
    int qblk = bid & 255;
    int wid  = tid >> 5, lane = tid & 31;
    int nA = qblk * QPB + wid * 2;
    int nB = nA + 1;

    const float* kb = kc + (size_t)b * 3 * NK;
    const float* qb = qc + (size_t)b * 3 * NQ;
    float qxA = qb[nA], qyA = qb[NQ + nA], qzA = qb[2 * NQ + nA];
    float qxB = qb[nB], qyB = qb[NQ + nB], qzB = qb[2 * NQ + nB];
    float qqA = __fadd_rn(__fadd_rn(__fmul_rn(qxA, qxA), __fmul_rn(qyA, qyA)),
                          __fmul_rn(qzA, qzA));
    float qqB = __fadd_rn(__fadd_rn(__fmul_rn(qxB, qxB), __fmul_rn(qyB, qyB)),
                          __fmul_rn(qzB, qzB));

    float bd = 3.4e38f;   // lanes 0-7: A's top-8 (sorted); lanes 8-15: B's
    int   bi = 0;
    float thrA = 3.4e38f, thrB = 3.4e38f;   // current 8th-best per query

    for (int m0 = 0; m0 < NK; m0 += KCHUNK) {
        __syncthreads();
        for (int m = tid; m < KCHUNK; m += 256) {
            float x = kb[m0 + m];
            float y = kb[NK + m0 + m];
            float z = kb[2 * NK + m0 + m];
            float kk = __fadd_rn(__fadd_rn(__fmul_rn(x, x), __fmul_rn(y, y)),
                                 __fmul_rn(z, z));
            sk[m] = make_float4(x, y, z, kk);
        }
        __syncthreads();

        for (int it = 0; it < KCHUNK / 32; it++) {
            float4 k4 = sk[it * 32 + lane];
            float dotA = __fmaf_rn(qzA, k4.z,
                          __fmaf_rn(qyA, k4.y, __fmul_rn(qxA, k4.x)));
            float dA = __fadd_rn(__fsub_rn(qqA, 2.0f * dotA), k4.w);
            float dotB = __fmaf_rn(qzB, k4.z,
                          __fmaf_rn(qyB, k4.y, __fmul_rn(qxB, k4.x)));
            float dB = __fadd_rn(__fsub_rn(qqB, 2.0f * dotB), k4.w);
            int base = m0 + it * 32;

            unsigned bal = __ballot_sync(FULLM, dA < thrA);
            while (bal) {                      // warp-uniform candidate loop
                int j = __ffs(bal) - 1; bal &= bal - 1;
                float dj = __shfl_sync(FULLM, dA, j);
                if (dj < thrA) {               // uniform re-check vs current
                    float bp = __shfl_up_sync(FULLM, bd, 1);
                    int   ip = __shfl_up_sync(FULLM, bi, 1);
                    if (lane < 8 && bd > dj) { // strictly-greater shift
                        bool tp = (lane > 0) && (bp > dj);
                        bd = tp ? bp : dj;
                        bi = tp ? ip : (base + j);
                    }
                    thrA = __shfl_sync(FULLM, bd, 7);
                }
            }
            bal = __ballot_sync(FULLM, dB < thrB);
            while (bal) {
                int j = __ffs(bal) - 1; bal &= bal - 1;
                float dj = __shfl_sync(FULLM, dB, j);
                if (dj < thrB) {
                    float bp = __shfl_up_sync(FULLM, bd, 1);
                    int   ip = __shfl_up_sync(FULLM, bi, 1);
                    if (lane >= 8 && lane < 16 && bd > dj) {
                        bool tp = (lane > 8) && (bp > dj);
                        bd = tp ? bp : dj;
                        bi = tp ? ip : (base + j);
                    }
                    thrB = __shfl_sync(FULLM, bd, 15);
                }
            }
        }
    }

    int* o = g_idx + ((size_t)b * NQ + nA) * KNN;
    if (lane < 8)       o[lane] = bi;
    else if (lane < 16) o[KNN + lane - 8] = bi;
}

// ---------------------------------------------------------------------------
// Gather + subtract + write (shared-staged, coalesced, streaming stores).
// out[b][c][n][k]     = KT[b][idx[n][k]][c] - qf[b][c][n]
// out[b][c+256][n][k] = qf[b][c][n]
// ---------------------------------------------------------------------------
#define NT 16
#define NP (NT * KNN)
#define CCH 64

__global__ void gather_kernel(const float* __restrict__ qf,
                              float* __restrict__ out) {
    __shared__ float S[CCH][NP + 1];
    __shared__ float Qs[NT][CCH + 1];
    __shared__ int   sidx[NP];

    int b   = blockIdx.y;
    int n0  = blockIdx.x * NT;
    int tid = threadIdx.x;  // 256

    if (tid < NP) sidx[tid] = g_idx[((size_t)b * NQ + n0) * KNN + tid];
    __syncthreads();

    const float* KTb = g_KT + (size_t)b * NK * NC;

    for (int c0 = 0; c0 < NC; c0 += CCH) {
        if (c0) __syncthreads();

#pragma unroll
        for (int i = tid; i < NP * (CCH / 4); i += 256) {
            int p  = i >> 4;
            int c4 = (i & 15) * 4;
            float4 v = *reinterpret_cast<const float4*>(
                &KTb[(size_t)sidx[p] * NC + c0 + c4]);
            S[c4 + 0][p] = v.x;
            S[c4 + 1][p] = v.y;
            S[c4 + 2][p] = v.z;
            S[c4 + 3][p] = v.w;
        }
#pragma unroll
        for (int i = tid; i < NT * CCH; i += 256) {
            int c = i >> 4, j = i & 15;
            Qs[j][c] = qf[((size_t)b * NC + c0 + c) * NQ + n0 + j];
        }
        __syncthreads();

#pragma unroll
        for (int i = tid; i < CCH * (NP / 4); i += 256) {
            int c = i >> 5;
            int p = (i & 31) * 4;
            float q = Qs[p >> 3][c];
            float4 d, qv;
            d.x = S[c][p + 0] - q;
            d.y = S[c][p + 1] - q;
            d.z = S[c][p + 2] - q;
            d.w = S[c][p + 3] - q;
            qv.x = q; qv.y = q; qv.z = q; qv.w = q;
            size_t ob = (((size_t)b * (2 * NC) + c0 + c) * NQ + n0) * KNN + p;
            __stcs(reinterpret_cast<float4*>(&out[ob]), d);
            __stcs(reinterpret_cast<float4*>(&out[ob + (size_t)NC * NQ * KNN]), qv);
        }
    }
}

// ---------------------------------------------------------------------------
extern "C" void kernel_launch(void* const* d_in, const int* in_sizes, int n_in,
                              void* d_out, int out_size) {
    const float* query_coords   = (const float*)d_in[0]; // (B,3,NQ)
    const float* query_features = (const float*)d_in[1]; // (B,C,NQ)
    const float* key_coords     = (const float*)d_in[2]; // (B,3,NK)
    const float* key_features   = (const float*)d_in[3]; // (B,C,NK)
    float* out = (float*)d_out;                          // (B,2C,NQ,K)

    prep_kernel<<<KNN_BLOCKS + TR_BLOCKS, 256>>>(query_coords, key_coords,
                                                 key_features);
    {
        dim3 grid(NQ / NT, NB);
        gather_kernel<<<grid, 256>>>(query_features, out);
    }
}

// round 6
// speedup vs baseline: 1.4808x; 1.0225x over previous
#include <cuda_runtime.h>
#include <cstdint>

#define NB 8
#define NC 256
#define NQ 4096
#define NK 4096
#define KNN 8
#define KCHUNK 2048
#define FULLM 0xffffffffu

// Scratch (static __device__ globals — allocation-free per harness rules)
__device__ float g_KT[(size_t)NB * NK * NC];   // key_features transposed (B,NK,C)
__device__ int   g_idx[(size_t)NB * NQ * KNN]; // knn indices

#define QPB 16                                  // queries per knn block (8 warps x 2)
#define KNN_BLOCKS (NB * (NQ / QPB))            // 2048
#define BC_BLOCKS  8192                         // broadcast-half writer blocks
#define TR_BLOCKS  (NB * (NK / 32) * (NC / 32)) // 8192
// broadcast: 256MB = 16M float4; 8192 blocks * 256 thr * 8 iters
#define BC_THREADS ((size_t)BC_BLOCKS * 256)
#define BC_TOTAL_F4 ((size_t)NB * NC * NQ * 2)  // 16777216

// ---------------------------------------------------------------------------
// Fused prep kernel, three block ranges (order = schedule priority):
//  [0, KNN_BLOCKS)        warp-cooperative kNN (2 queries per warp) — long pole
//  [+, +BC_BLOCKS)        broadcast half of output: out[b][256+c][n][k]=qf[b][c][n]
//  [+, +TR_BLOCKS)        transpose key_features (B,C,NK) -> g_KT (B,NK,C)
// Ranges 2 and 3 are DRAM work that hides under range 1's compute.
//
// kNN semantics (bit-exact vs XLA reference):
//   qq  = rn(rn(rn(x*x)+rn(y*y))+rn(z*z))           (no fma)
//   dot = fma(qz,kz, fma(qy,ky, rn(qx*kx)))         (GEMM k-ascending chain)
//   d   = rn(rn(qq - 2*dot) + kk)                   (2*dot exact)
// Ascending key order + strict '<' entry + strictly-greater shift
// => identical tie behavior to jax.lax.top_k.
// ---------------------------------------------------------------------------
__global__ void prep_kernel(const float* __restrict__ qc,
                            const float* __restrict__ kc,
                            const float* __restrict__ kf,
                            const float* __restrict__ qf,
                            float* __restrict__ out) {
    __shared__ __align__(16) unsigned char smem_raw[KCHUNK * 16]; // 32KB
    int tid = threadIdx.x;  // 256

    if (blockIdx.x >= KNN_BLOCKS && blockIdx.x < KNN_BLOCKS + BC_BLOCKS) {
        // ------------- broadcast half: pure coalesced streaming write -----
        float4* out4 = reinterpret_cast<float4*>(out);
        size_t t0 = ((size_t)(blockIdx.x - KNN_BLOCKS) * 256 + tid);
#pragma unroll
        for (int j = 0; j < 8; j++) {
            size_t G = t0 + (size_t)j * BC_THREADS;  // [0, 16M)
            int n = (int)((G >> 1) & (NQ - 1));
            int c = (int)((G >> 13) & (NC - 1));
            int b = (int)(G >> 21);
            float q = qf[((size_t)b * NC + c) * NQ + n];
            float4 v = make_float4(q, q, q, q);
            __stcs(&out4[G + ((size_t)b + 1) * 2097152], v);
        }
        return;
    }

    if (blockIdx.x >= KNN_BLOCKS + BC_BLOCKS) {
        // ---------------- transpose (B,C,NK) -> (B,NK,C) ----------------
        float (*t)[33] = reinterpret_cast<float (*)[33]>(smem_raw);
        int idx = blockIdx.x - KNN_BLOCKS - BC_BLOCKS;
        int b   = idx >> 10;
        int rem = idx & 1023;
        int n0  = (rem & 127) * 32;
        int c0  = (rem >> 7) * 32;
        int tx = tid & 31, ty0 = tid >> 5;
#pragma unroll
        for (int dy = 0; dy < 32; dy += 8) {
            int ty = ty0 + dy;
            t[ty][tx] = kf[((size_t)b * NC + c0 + ty) * NK + n0 + tx];
        }
        __syncthreads();
#pragma unroll
        for (int dy = 0; dy < 32; dy += 8) {
            int ty = ty0 + dy;
            g_KT[((size_t)b * NK + n0 + ty) * NC + c0 + tx] = t[tx][ty];
        }
        return;
    }

    // ----------------------------- kNN ----------------------------------
    float4* sk = reinterpret_cast<float4*>(smem_raw);  // KCHUNK float4
    int bid  = blockIdx.x;
    int b    = bid >> 8;          // / (NQ/QPB = 256)
    int qblk = bid & 255;
    int wid  = tid >> 5, lane = tid & 31;
    int nA = qblk * QPB + wid * 2;
    int nB = nA + 1;

    const float* kb = kc + (size_t)b * 3 * NK;
    const float* qb = qc + (size_t)b * 3 * NQ;
    float qxA = qb[nA], qyA = qb[NQ + nA], qzA = qb[2 * NQ + nA];
    float qxB = qb[nB], qyB = qb[NQ + nB], qzB = qb[2 * NQ + nB];
    float qqA = __fadd_rn(__fadd_rn(__fmul_rn(qxA, qxA), __fmul_rn(qyA, qyA)),
                          __fmul_rn(qzA, qzA));
    float qqB = __fadd_rn(__fadd_rn(__fmul_rn(qxB, qxB), __fmul_rn(qyB, qyB)),
                          __fmul_rn(qzB, qzB));

    float bd = 3.4e38f;   // lanes 0-7: A's sorted top-8; lanes 8-15: B's
    int   bi = 0;
    float thrA = 3.4e38f, thrB = 3.4e38f;

    for (int m0 = 0; m0 < NK; m0 += KCHUNK) {
        __syncthreads();
        for (int m = tid; m < KCHUNK; m += 256) {
            float x = kb[m0 + m];
            float y = kb[NK + m0 + m];
            float z = kb[2 * NK + m0 + m];
            float kk = __fadd_rn(__fadd_rn(__fmul_rn(x, x), __fmul_rn(y, y)),
                                 __fmul_rn(z, z));
            sk[m] = make_float4(x, y, z, kk);
        }
        __syncthreads();

        for (int it = 0; it < KCHUNK / 32; it++) {
            float4 k4 = sk[it * 32 + lane];
            float dotA = __fmaf_rn(qzA, k4.z,
                          __fmaf_rn(qyA, k4.y, __fmul_rn(qxA, k4.x)));
            float dA = __fadd_rn(__fsub_rn(qqA, 2.0f * dotA), k4.w);
            float dotB = __fmaf_rn(qzB, k4.z,
                          __fmaf_rn(qyB, k4.y, __fmul_rn(qxB, k4.x)));
            float dB = __fadd_rn(__fsub_rn(qqB, 2.0f * dotB), k4.w);
            int base = m0 + it * 32;

            unsigned bal = __ballot_sync(FULLM, dA < thrA);
            while (bal) {                      // warp-uniform candidate loop
                int j = __ffs(bal) - 1; bal &= bal - 1;
                float dj = __shfl_sync(FULLM, dA, j);
                if (dj < thrA) {
                    float bp = __shfl_up_sync(FULLM, bd, 1);
                    int   ip = __shfl_up_sync(FULLM, bi, 1);
                    if (lane < 8 && bd > dj) {
                        bool tp = (lane > 0) && (bp > dj);
                        bd = tp ? bp : dj;
                        bi = tp ? ip : (base + j);
                    }
                    thrA = __shfl_sync(FULLM, bd, 7);
                }
            }
            bal = __ballot_sync(FULLM, dB < thrB);
            while (bal) {
                int j = __ffs(bal) - 1; bal &= bal - 1;
                float dj = __shfl_sync(FULLM, dB, j);
                if (dj < thrB) {
                    float bp = __shfl_up_sync(FULLM, bd, 1);
                    int   ip = __shfl_up_sync(FULLM, bi, 1);
                    if (lane >= 8 && lane < 16 && bd > dj) {
                        bool tp = (lane > 8) && (bp > dj);
                        bd = tp ? bp : dj;
                        bi = tp ? ip : (base + j);
                    }
                    thrB = __shfl_sync(FULLM, bd, 15);
                }
            }
        }
    }

    int* o = g_idx + ((size_t)b * NQ + nA) * KNN;
    if (lane < 8)       o[lane] = bi;
    else if (lane < 16) o[KNN + lane - 8] = bi;
}

// ---------------------------------------------------------------------------
// Gather kernel: diff half only.
// out[b][c][n][k] = KT[b][idx[n][k]][c] - qf[b][c][n],  c in [0,256)
// Shared-staged transpose for coalesced gather reads AND coalesced writes.
// ---------------------------------------------------------------------------
#define NT 16
#define NP (NT * KNN)
#define CCH 64

__global__ void gather_kernel(const float* __restrict__ qf,
                              float* __restrict__ out) {
    __shared__ float S[CCH][NP + 1];
    __shared__ float Qs[NT][CCH + 1];
    __shared__ int   sidx[NP];

    int b   = blockIdx.y;
    int n0  = blockIdx.x * NT;
    int tid = threadIdx.x;  // 256

    if (tid < NP) sidx[tid] = g_idx[((size_t)b * NQ + n0) * KNN + tid];
    __syncthreads();

    const float* KTb = g_KT + (size_t)b * NK * NC;

    for (int c0 = 0; c0 < NC; c0 += CCH) {
        if (c0) __syncthreads();

#pragma unroll
        for (int i = tid; i < NP * (CCH / 4); i += 256) {
            int p  = i >> 4;
            int c4 = (i & 15) * 4;
            float4 v = *reinterpret_cast<const float4*>(
                &KTb[(size_t)sidx[p] * NC + c0 + c4]);
            S[c4 + 0][p] = v.x;
            S[c4 + 1][p] = v.y;
            S[c4 + 2][p] = v.z;
            S[c4 + 3][p] = v.w;
        }
#pragma unroll
        for (int i = tid; i < NT * CCH; i += 256) {
            int c = i >> 4, j = i & 15;
            Qs[j][c] = qf[((size_t)b * NC + c0 + c) * NQ + n0 + j];
        }
        __syncthreads();

#pragma unroll
        for (int i = tid; i < CCH * (NP / 4); i += 256) {
            int c = i >> 5;
            int p = (i & 31) * 4;
            float q = Qs[p >> 3][c];
            float4 d;
            d.x = S[c][p + 0] - q;
            d.y = S[c][p + 1] - q;
            d.z = S[c][p + 2] - q;
            d.w = S[c][p + 3] - q;
            size_t ob = (((size_t)b * (2 * NC) + c0 + c) * NQ + n0) * KNN + p;
            __stcs(reinterpret_cast<float4*>(&out[ob]), d);
        }
    }
}

// ---------------------------------------------------------------------------
extern "C" void kernel_launch(void* const* d_in, const int* in_sizes, int n_in,
                              void* d_out, int out_size) {
    const float* query_coords   = (const float*)d_in[0]; // (B,3,NQ)
    const float* query_features = (const float*)d_in[1]; // (B,C,NQ)
    const float* key_coords     = (const float*)d_in[2]; // (B,3,NK)
    const float* key_features   = (const float*)d_in[3]; // (B,C,NK)
    float* out = (float*)d_out;                          // (B,2C,NQ,K)

    prep_kernel<<<KNN_BLOCKS + BC_BLOCKS + TR_BLOCKS, 256>>>(
        query_coords, key_coords, key_features, query_features, out);
    {
        dim3 grid(NQ / NT, NB);
        gather_kernel<<<grid, 256>>>(query_features, out);
    }
}